// round 2
// baseline (speedup 1.0000x reference)
#include <cuda_runtime.h>

#define BB    4096
#define TT    50
#define IN_W  4
#define HH    256
#define G4    1024   // 4*H
#define KK    3
#define FSS   6
#define BM    16
#define NTHR  256
#define NBLK  (BB/BM)   // 256

// ---------------- device scratch (no allocations allowed) ----------------
__device__ float g_h0[BB*HH], g_c0[BB*HH], g_h1[BB*HH], g_c1[BB*HH];
// packed weights: per matrix [H/4][1024 rows][4 k-values] for coalesced float4 loads
__device__ float p_Whh0 [(HH/4)*G4*4];
__device__ float p_Wih1 [(HH/4)*G4*4];
__device__ float p_Whh1 [(HH/4)*G4*4];
__device__ float p_dWhh0[KK*(HH/4)*G4*4];
__device__ float p_dWih1[KK*(HH/4)*G4*4];
__device__ float p_dWhh1[KK*(HH/4)*G4*4];

// ---------------- helpers ----------------
__device__ __forceinline__ float sigf(float x){ return 1.0f/(1.0f + __expf(-x)); }
__device__ __forceinline__ float tanh_fast(float x){
  x = fminf(fmaxf(x, -10.0f), 10.0f);
  float e = __expf(2.0f*x);
  return (e - 1.0f)/(e + 1.0f);
}

// gates accumulation: a{g}[b] += W[g*H+j][k] * hsrc[b][k] over k=0..255
__device__ __forceinline__ void accum_block(
    float (&a0)[BM], float (&a1)[BM], float (&a2)[BM], float (&a3)[BM],
    const float4* __restrict__ P, const float* __restrict__ hsrc, int j)
{
  #pragma unroll 1
  for (int k4 = 0; k4 < HH/4; k4++){
    const float4* wp = P + (size_t)k4 * G4;
    float4 w0 = wp[j];
    float4 w1 = wp[HH   + j];
    float4 w2 = wp[2*HH + j];
    float4 w3 = wp[3*HH + j];
    #pragma unroll
    for (int b = 0; b < BM; b++){
      float4 hv = *(const float4*)(hsrc + b*HH + k4*4);
      a0[b] = fmaf(w0.x, hv.x, a0[b]); a0[b] = fmaf(w0.y, hv.y, a0[b]);
      a0[b] = fmaf(w0.z, hv.z, a0[b]); a0[b] = fmaf(w0.w, hv.w, a0[b]);
      a1[b] = fmaf(w1.x, hv.x, a1[b]); a1[b] = fmaf(w1.y, hv.y, a1[b]);
      a1[b] = fmaf(w1.z, hv.z, a1[b]); a1[b] = fmaf(w1.w, hv.w, a1[b]);
      a2[b] = fmaf(w2.x, hv.x, a2[b]); a2[b] = fmaf(w2.y, hv.y, a2[b]);
      a2[b] = fmaf(w2.z, hv.z, a2[b]); a2[b] = fmaf(w2.w, hv.w, a2[b]);
      a3[b] = fmaf(w3.x, hv.x, a3[b]); a3[b] = fmaf(w3.y, hv.y, a3[b]);
      a3[b] = fmaf(w3.z, hv.z, a3[b]); a3[b] = fmaf(w3.w, hv.w, a3[b]);
    }
  }
}

__device__ __forceinline__ void cell_update(
    float* __restrict__ hs, float* __restrict__ cs, int j,
    float (&a0)[BM], float (&a1)[BM], float (&a2)[BM], float (&a3)[BM])
{
  // caller must have __syncthreads() before this (all smem reads complete)
  #pragma unroll
  for (int b = 0; b < BM; b++){
    float ig = sigf(a0[b]);
    float fg = sigf(a1[b]);
    float gg = tanh_fast(a2[b]);
    float og = sigf(a3[b]);
    float c  = fg * cs[b*HH + j] + ig * gg;
    cs[b*HH + j] = c;
    hs[b*HH + j] = og * tanh_fast(c);
  }
}

// ---------------- weight repack: W[m][row][k] -> P[m][k/4][row][4] ----------------
__global__ void pack_kernel(const float* __restrict__ src, float* __restrict__ dst, int count)
{
  int idx = blockIdx.x * blockDim.x + threadIdx.x;
  int total = count * G4 * HH;
  if (idx < total){
    int m = idx / (G4*HH);
    int r = (idx / HH) % G4;
    int k = idx % HH;
    dst[(size_t)m*(HH/4)*G4*4 + (size_t)(k>>2)*G4*4 + r*4 + (k&3)] = src[idx];
  }
}

// ---------------- the fused persistent kernel ----------------
__global__ void __launch_bounds__(NTHR, 2) lstm_fused_kernel(
    const float* __restrict__ x,
    const float* __restrict__ eWih0,
    const float* __restrict__ ebih0, const float* __restrict__ ebhh0,
    const float* __restrict__ ebih1, const float* __restrict__ ebhh1,
    const float* __restrict__ dWih0,
    const float* __restrict__ dbih0, const float* __restrict__ dbhh0,
    const float* __restrict__ dbih1, const float* __restrict__ dbhh1,
    const float* __restrict__ headW, const float* __restrict__ headb,
    const float* __restrict__ confW, const float* __restrict__ confb,
    float* __restrict__ out)
{
  extern __shared__ float sm[];
  float* hs0   = sm;                 // BM*HH
  float* cs0   = hs0   + BM*HH;
  float* hs1   = cs0   + BM*HH;
  float* cs1   = hs1   + BM*HH;
  float* bias0 = cs1   + BM*HH;      // G4
  float* bias1 = bias0 + G4;         // G4
  float* xin   = bias1 + G4;         // BM*IN_W
  float* tmp   = xin   + BM*IN_W;    // BM*KK

  const int j  = threadIdx.x;        // hidden unit
  const int b0 = blockIdx.x * BM;    // first batch row of this block

  // combined biases + zero state
  #pragma unroll
  for (int g = 0; g < 4; g++){
    bias0[g*HH + j] = ebih0[g*HH + j] + ebhh0[g*HH + j];
    bias1[g*HH + j] = ebih1[g*HH + j] + ebhh1[g*HH + j];
  }
  #pragma unroll
  for (int b = 0; b < BM; b++){
    hs0[b*HH + j] = 0.f; cs0[b*HH + j] = 0.f;
    hs1[b*HH + j] = 0.f; cs1[b*HH + j] = 0.f;
  }
  // encoder layer-0 input weights (tiny: 4 per gate), constant over time
  float4 wi0[4];
  #pragma unroll
  for (int g = 0; g < 4; g++)
    wi0[g] = *(const float4*)(eWih0 + (size_t)(g*HH + j) * IN_W);
  __syncthreads();

  float a0[BM], a1[BM], a2[BM], a3[BM];

  // ================= encoder: 50 steps =================
  for (int t = 0; t < TT; t++){
    if (j < BM*IN_W)
      xin[j] = x[(size_t)(b0 + j/IN_W)*TT*IN_W + t*IN_W + (j & 3)];
    __syncthreads();

    // layer 0: bias + Wih0 @ x_t
    #pragma unroll
    for (int b = 0; b < BM; b++){
      float x0 = xin[b*4+0], x1 = xin[b*4+1], x2 = xin[b*4+2], x3 = xin[b*4+3];
      a0[b] = bias0[       j] + wi0[0].x*x0 + wi0[0].y*x1 + wi0[0].z*x2 + wi0[0].w*x3;
      a1[b] = bias0[  HH + j] + wi0[1].x*x0 + wi0[1].y*x1 + wi0[1].z*x2 + wi0[1].w*x3;
      a2[b] = bias0[2*HH + j] + wi0[2].x*x0 + wi0[2].y*x1 + wi0[2].z*x2 + wi0[2].w*x3;
      a3[b] = bias0[3*HH + j] + wi0[3].x*x0 + wi0[3].y*x1 + wi0[3].z*x2 + wi0[3].w*x3;
    }
    accum_block(a0,a1,a2,a3, (const float4*)p_Whh0, hs0, j);
    __syncthreads();
    cell_update(hs0, cs0, j, a0,a1,a2,a3);
    __syncthreads();

    // layer 1: bias + Wih1 @ h0 + Whh1 @ h1
    #pragma unroll
    for (int b = 0; b < BM; b++){
      a0[b] = bias1[       j];
      a1[b] = bias1[  HH + j];
      a2[b] = bias1[2*HH + j];
      a3[b] = bias1[3*HH + j];
    }
    accum_block(a0,a1,a2,a3, (const float4*)p_Wih1, hs0, j);
    accum_block(a0,a1,a2,a3, (const float4*)p_Whh1, hs1, j);
    __syncthreads();
    cell_update(hs1, cs1, j, a0,a1,a2,a3);
    __syncthreads();
  }

  // save encoder final state (needed fresh per decoder mode)
  #pragma unroll
  for (int b = 0; b < BM; b++){
    size_t gi = (size_t)(b0 + b)*HH + j;
    g_h0[gi] = hs0[b*HH + j];  g_c0[gi] = cs0[b*HH + j];
    g_h1[gi] = hs1[b*HH + j];  g_c1[gi] = cs1[b*HH + j];
  }

  // ================= confidence head (softmax over K) =================
  if (j < BM*KK){
    int b = j / KK, kk = j % KK;
    float s = confb[kk];
    const float* cw = confW + (size_t)kk*HH;
    for (int u = 0; u < HH; u++) s += hs1[b*HH + u] * cw[u];
    tmp[j] = s;
  }
  __syncthreads();
  if (j < BM){
    float l0 = tmp[j*KK], l1 = tmp[j*KK+1], l2 = tmp[j*KK+2];
    float m  = fmaxf(l0, fmaxf(l1, l2));
    float e0 = __expf(l0-m), e1 = __expf(l1-m), e2 = __expf(l2-m);
    float inv = 1.0f/(e0+e1+e2);
    size_t base = (size_t)BB*KK*FSS*2 + (size_t)(b0 + j)*KK;
    out[base+0] = e0*inv; out[base+1] = e1*inv; out[base+2] = e2*inv;
  }

  // ================= decoder: K modes x FS steps =================
  for (int km = 0; km < KK; km++){
    __syncthreads();
    // reload encoder state, per-mode biases/weights
    #pragma unroll
    for (int b = 0; b < BM; b++){
      size_t gi = (size_t)(b0 + b)*HH + j;
      hs0[b*HH + j] = g_h0[gi];  cs0[b*HH + j] = g_c0[gi];
      hs1[b*HH + j] = g_h1[gi];  cs1[b*HH + j] = g_c1[gi];
    }
    #pragma unroll
    for (int g = 0; g < 4; g++){
      bias0[g*HH + j] = dbih0[(size_t)km*G4 + g*HH + j] + dbhh0[(size_t)km*G4 + g*HH + j];
      bias1[g*HH + j] = dbih1[(size_t)km*G4 + g*HH + j] + dbhh1[(size_t)km*G4 + g*HH + j];
    }
    float2 dwi[4];
    #pragma unroll
    for (int g = 0; g < 4; g++)
      dwi[g] = *(const float2*)(dWih0 + ((size_t)km*G4 + g*HH + j) * 2);
    if (j < BM*2)
      xin[j] = x[(size_t)(b0 + j/2)*TT*IN_W + (TT-1)*IN_W + (j & 1)];
    __syncthreads();

    const float4* Pd0 = (const float4*)p_dWhh0 + (size_t)km*(HH/4)*G4;
    const float4* Pi1 = (const float4*)p_dWih1 + (size_t)km*(HH/4)*G4;
    const float4* Ph1 = (const float4*)p_dWhh1 + (size_t)km*(HH/4)*G4;

    for (int s = 0; s < FSS; s++){
      // layer 0
      #pragma unroll
      for (int b = 0; b < BM; b++){
        float i0 = xin[b*2], i1 = xin[b*2+1];
        a0[b] = bias0[       j] + dwi[0].x*i0 + dwi[0].y*i1;
        a1[b] = bias0[  HH + j] + dwi[1].x*i0 + dwi[1].y*i1;
        a2[b] = bias0[2*HH + j] + dwi[2].x*i0 + dwi[2].y*i1;
        a3[b] = bias0[3*HH + j] + dwi[3].x*i0 + dwi[3].y*i1;
      }
      accum_block(a0,a1,a2,a3, Pd0, hs0, j);
      __syncthreads();
      cell_update(hs0, cs0, j, a0,a1,a2,a3);
      __syncthreads();

      // layer 1
      #pragma unroll
      for (int b = 0; b < BM; b++){
        a0[b] = bias1[       j];
        a1[b] = bias1[  HH + j];
        a2[b] = bias1[2*HH + j];
        a3[b] = bias1[3*HH + j];
      }
      accum_block(a0,a1,a2,a3, Pi1, hs0, j);
      accum_block(a0,a1,a2,a3, Ph1, hs1, j);
      __syncthreads();
      cell_update(hs1, cs1, j, a0,a1,a2,a3);
      __syncthreads();

      // head: pred[b][o] = h1[b] . headW[km][o] + headb[km][o]
      if (j < BM*2){
        int b = j >> 1, o = j & 1;
        float p = headb[(size_t)km*2 + o];
        const float* hw = headW + ((size_t)km*2 + o)*HH;
        for (int u = 0; u < HH; u++) p += hs1[b*HH + u] * hw[u];
        out[(size_t)(b0 + b)*(KK*FSS*2) + km*(FSS*2) + s*2 + o] = p;
        xin[b*2 + o] = p;  // autoregressive feedback
      }
      __syncthreads();
    }
  }
}

// ---------------- launch ----------------
extern "C" void kernel_launch(void* const* d_in, const int* in_sizes, int n_in,
                              void* d_out, int out_size)
{
  const float* x     = (const float*)d_in[0];
  const float* eWih0 = (const float*)d_in[1];
  const float* eWhh0 = (const float*)d_in[2];
  const float* ebih0 = (const float*)d_in[3];
  const float* ebhh0 = (const float*)d_in[4];
  const float* eWih1 = (const float*)d_in[5];
  const float* eWhh1 = (const float*)d_in[6];
  const float* ebih1 = (const float*)d_in[7];
  const float* ebhh1 = (const float*)d_in[8];
  const float* dWih0 = (const float*)d_in[9];
  const float* dWhh0 = (const float*)d_in[10];
  const float* dbih0 = (const float*)d_in[11];
  const float* dbhh0 = (const float*)d_in[12];
  const float* dWih1 = (const float*)d_in[13];
  const float* dWhh1 = (const float*)d_in[14];
  const float* dbih1 = (const float*)d_in[15];
  const float* dbhh1 = (const float*)d_in[16];
  const float* headW = (const float*)d_in[17];
  const float* headb = (const float*)d_in[18];
  const float* confW = (const float*)d_in[19];
  const float* confb = (const float*)d_in[20];
  float* out = (float*)d_out;

  float *pp_Whh0, *pp_Wih1, *pp_Whh1, *pp_dWhh0, *pp_dWih1, *pp_dWhh1;
  cudaGetSymbolAddress((void**)&pp_Whh0,  p_Whh0);
  cudaGetSymbolAddress((void**)&pp_Wih1,  p_Wih1);
  cudaGetSymbolAddress((void**)&pp_Whh1,  p_Whh1);
  cudaGetSymbolAddress((void**)&pp_dWhh0, p_dWhh0);
  cudaGetSymbolAddress((void**)&pp_dWih1, p_dWih1);
  cudaGetSymbolAddress((void**)&pp_dWhh1, p_dWhh1);

  const int PT = 256;
  int n1 = G4*HH,      g1 = (n1 + PT - 1)/PT;       // one matrix
  int n3 = KK*G4*HH,   g3 = (n3 + PT - 1)/PT;       // three matrices
  pack_kernel<<<g1, PT>>>(eWhh0, pp_Whh0, 1);
  pack_kernel<<<g1, PT>>>(eWih1, pp_Wih1, 1);
  pack_kernel<<<g1, PT>>>(eWhh1, pp_Whh1, 1);
  pack_kernel<<<g3, PT>>>(dWhh0, pp_dWhh0, KK);
  pack_kernel<<<g3, PT>>>(dWih1, pp_dWih1, KK);
  pack_kernel<<<g3, PT>>>(dWhh1, pp_dWhh1, KK);

  const int SMEM_BYTES = (4*BM*HH + 2*G4 + BM*IN_W + BM*KK) * (int)sizeof(float);
  cudaFuncSetAttribute(lstm_fused_kernel,
                       cudaFuncAttributeMaxDynamicSharedMemorySize, SMEM_BYTES);

  lstm_fused_kernel<<<NBLK, NTHR, SMEM_BYTES>>>(
      x, eWih0, ebih0, ebhh0, ebih1, ebhh1,
      dWih0, dbih0, dbhh0, dbih1, dbhh1,
      headW, headb, confW, confb, out);
}